// round 6
// baseline (speedup 1.0000x reference)
#include <cuda_runtime.h>
#include <cuda_bf16.h>
#include <cstdint>

// Problem constants
#define BB 32
#define NS 262144
#define HH 256
#define WW 256
#define HWSZ (HH * WW)

constexpr int SEGS = 32;

// Per-(batch, segment) partial bounds: x = xmin, y = xmax, z = ymin, w = ymax.
__device__ float4 g_part[BB][SEGS];

// grid = (SEGS, BB) = 1024 blocks, block = 256.
// Computes partial min/max AND zeroes a slice of the output field.
__global__ __launch_bounds__(256) void minmax_kernel(const float* __restrict__ spatial,
                                                     float4* __restrict__ out4) {
    const int b = blockIdx.y;
    const int seg_elems = HWSZ / SEGS;                 // 2048 floats
    const float* base = spatial + (size_t)b * 2 * HWSZ + (size_t)blockIdx.x * seg_elems;
    const float4* vx = reinterpret_cast<const float4*>(base);
    const float4* vy = reinterpret_cast<const float4*>(base + HWSZ);

    // 512 float4 per channel / 256 threads = 2 each. Front-batch all 4 loads.
    float4 ax[2], ay[2];
    #pragma unroll
    for (int j = 0; j < 2; j++) ax[j] = vx[threadIdx.x + j * 256];
    #pragma unroll
    for (int j = 0; j < 2; j++) ay[j] = vy[threadIdx.x + j * 256];

    // Zero this block's slice of the output field:
    // 2M floats / 1024 blocks = 2048 floats = 512 float4 per block.
    {
        const size_t blk = (size_t)b * SEGS + blockIdx.x;       // 0..1023
        float4* oz = out4 + blk * 512;
        const float4 z = make_float4(0.f, 0.f, 0.f, 0.f);
        #pragma unroll
        for (int j = 0; j < 2; j++) oz[threadIdx.x + j * 256] = z;
    }

    float xmn = 3.4e38f, xmx = -3.4e38f, ymn = 3.4e38f, ymx = -3.4e38f;
    #pragma unroll
    for (int j = 0; j < 2; j++) {
        xmn = fminf(xmn, fminf(fminf(ax[j].x, ax[j].y), fminf(ax[j].z, ax[j].w)));
        xmx = fmaxf(xmx, fmaxf(fmaxf(ax[j].x, ax[j].y), fmaxf(ax[j].z, ax[j].w)));
        ymn = fminf(ymn, fminf(fminf(ay[j].x, ay[j].y), fminf(ay[j].z, ay[j].w)));
        ymx = fmaxf(ymx, fmaxf(fmaxf(ay[j].x, ay[j].y), fmaxf(ay[j].z, ay[j].w)));
    }

    #pragma unroll
    for (int off = 16; off > 0; off >>= 1) {
        xmn = fminf(xmn, __shfl_xor_sync(0xFFFFFFFFu, xmn, off));
        xmx = fmaxf(xmx, __shfl_xor_sync(0xFFFFFFFFu, xmx, off));
        ymn = fminf(ymn, __shfl_xor_sync(0xFFFFFFFFu, ymn, off));
        ymx = fmaxf(ymx, __shfl_xor_sync(0xFFFFFFFFu, ymx, off));
    }

    __shared__ float4 s[8];
    const int wid = threadIdx.x >> 5;
    const int lid = threadIdx.x & 31;
    if (lid == 0) s[wid] = make_float4(xmn, xmx, ymn, ymx);
    __syncthreads();
    if (threadIdx.x == 0) {
        float4 r = s[0];
        #pragma unroll
        for (int w = 1; w < 8; w++) {
            r.x = fminf(r.x, s[w].x);
            r.y = fmaxf(r.y, s[w].y);
            r.z = fminf(r.z, s[w].z);
            r.w = fmaxf(r.w, s[w].w);
        }
        g_part[b][blockIdx.x] = r;
    }
}

// Scatter: accumulate ONLY masked point_rates; gia multiply deferred.
constexpr int TPB = 256;
constexpr int IT  = 16;

__global__ __launch_bounds__(TPB) void scatter_kernel(
    const float*  __restrict__ point_rates,
    const float2* __restrict__ coords,
    float*        __restrict__ out)
{
    const int b = blockIdx.y;
    const float* pr = point_rates + (size_t)b * NS;
    float* ob = out + (size_t)b * HWSZ;

    const int base = blockIdx.x * (TPB * IT) + threadIdx.x;

    // Issue ALL payload loads first so they're in flight while the bounds
    // prologue resolves (L2 hits). BAR does not block pending LDG->reg.
    float2 c[IT];
    float  rate[IT];
    #pragma unroll
    for (int j = 0; j < IT; j++) c[j] = coords[base + j * TPB];
    #pragma unroll
    for (int j = 0; j < IT; j++) rate[j] = pr[base + j * TPB];

    // Bounds prologue: one warp reduces the SEGS(=32) partials, one per lane.
    __shared__ float4 sb;
    if (threadIdx.x < 32) {
        float4 p = g_part[b][threadIdx.x];
        float xmn = p.x, xmx = p.y, ymn = p.z, ymx = p.w;
        #pragma unroll
        for (int off = 16; off > 0; off >>= 1) {
            xmn = fminf(xmn, __shfl_xor_sync(0xFFFFFFFFu, xmn, off));
            xmx = fmaxf(xmx, __shfl_xor_sync(0xFFFFFFFFu, xmx, off));
            ymn = fminf(ymn, __shfl_xor_sync(0xFFFFFFFFu, ymn, off));
            ymx = fmaxf(ymx, __shfl_xor_sync(0xFFFFFFFFu, ymx, off));
        }
        if (threadIdx.x == 0) sb = make_float4(xmn, xmx, ymn, ymx);
    }
    __syncthreads();

    const float xmin = sb.x, xmax = sb.y, ymin = sb.z, ymax = sb.w;
    const float dx = __fsub_rn(xmax, xmin);
    const float dy = __fsub_rn(ymax, ymin);

    #pragma unroll
    for (int j = 0; j < IT; j++) {
        const bool iv = (c[j].x >= xmin) && (c[j].x <= xmax) &&
                        (c[j].y >= ymin) && (c[j].y <= ymax);
        // Match reference bit-exactly: strict IEEE rn sub/div/mul, then
        // round-half-even (== jnp.round) before clip.
        const float nx = __fdiv_rn(__fsub_rn(c[j].x, xmin), dx);
        const float ny = __fdiv_rn(__fsub_rn(c[j].y, ymin), dy);
        int px = __float2int_rn(__fmul_rn(nx, 255.0f));
        int py = __float2int_rn(__fmul_rn(ny, 255.0f));
        px = min(max(px, 0), WW - 1);
        py = min(max(py, 0), HH - 1);
        if (iv) {
            atomicAdd(&ob[py * WW + px], rate[j]);   // RED.ADD, no return
        }
    }
}

// Streaming finalize: out[i] = rate_sum[i] * gia[i].
constexpr int MTPB = 256;
constexpr int MIT  = 2;

__global__ __launch_bounds__(MTPB) void mul_kernel(const float4* __restrict__ gia,
                                                   float4* __restrict__ out,
                                                   int n4)
{
    int i = blockIdx.x * MTPB + threadIdx.x;
    const int stride = gridDim.x * MTPB;
    for (; i < n4; i += stride) {
        float4 o = out[i];
        float4 g = gia[i];
        o.x = __fmul_rn(o.x, g.x);
        o.y = __fmul_rn(o.y, g.y);
        o.z = __fmul_rn(o.z, g.z);
        o.w = __fmul_rn(o.w, g.w);
        out[i] = o;
    }
}

extern "C" void kernel_launch(void* const* d_in, const int* in_sizes, int n_in,
                              void* d_out, int out_size)
{
    const float*  point_rates = (const float*)d_in[0];   // (B, NS)
    const float*  spatial     = (const float*)d_in[1];   // (B, 2, H, W)
    const float*  gia         = (const float*)d_in[2];   // (B, H, W)
    const float2* coords      = (const float2*)d_in[3];  // (NS, 2)
    float* out = (float*)d_out;                          // (B, 1, H, W)

    // Per-batch min/max partials + output zeroing (no memset node)
    dim3 mg(SEGS, BB);
    minmax_kernel<<<mg, 256>>>(spatial, (float4*)out);

    // Scatter-add of masked rates
    dim3 sg(NS / (TPB * IT), BB);
    scatter_kernel<<<sg, TPB>>>(point_rates, coords, out);

    // Finalize: multiply by gia
    const int n4 = (BB * HWSZ) / 4;   // 524288
    mul_kernel<<<n4 / (MTPB * MIT), MTPB>>>((const float4*)gia, (float4*)out, n4);
}

// round 7
// speedup vs baseline: 1.0207x; 1.0207x over previous
#include <cuda_runtime.h>
#include <cuda_bf16.h>
#include <cstdint>

// Problem constants
#define BB 32
#define NS 262144
#define HH 256
#define WW 256
#define HWSZ (HH * WW)

constexpr int SEGS = 32;

// Per-(batch, segment) partial bounds: x = xmin, y = xmax, z = ymin, w = ymax.
__device__ float4 g_part[BB][SEGS];

// grid = (SEGS, BB) = 1024 blocks, block = 256.
// Computes partial min/max AND zeroes a slice of the output field.
__global__ __launch_bounds__(256) void minmax_kernel(const float* __restrict__ spatial,
                                                     float4* __restrict__ out4) {
    const int b = blockIdx.y;
    const int seg_elems = HWSZ / SEGS;                 // 2048 floats
    const float* base = spatial + (size_t)b * 2 * HWSZ + (size_t)blockIdx.x * seg_elems;
    const float4* vx = reinterpret_cast<const float4*>(base);
    const float4* vy = reinterpret_cast<const float4*>(base + HWSZ);

    float4 ax[2], ay[2];
    #pragma unroll
    for (int j = 0; j < 2; j++) ax[j] = vx[threadIdx.x + j * 256];
    #pragma unroll
    for (int j = 0; j < 2; j++) ay[j] = vy[threadIdx.x + j * 256];

    // Zero this block's slice of the output field (2048 floats / block).
    {
        const size_t blk = (size_t)b * SEGS + blockIdx.x;       // 0..1023
        float4* oz = out4 + blk * 512;
        const float4 z = make_float4(0.f, 0.f, 0.f, 0.f);
        #pragma unroll
        for (int j = 0; j < 2; j++) oz[threadIdx.x + j * 256] = z;
    }

    float xmn = 3.4e38f, xmx = -3.4e38f, ymn = 3.4e38f, ymx = -3.4e38f;
    #pragma unroll
    for (int j = 0; j < 2; j++) {
        xmn = fminf(xmn, fminf(fminf(ax[j].x, ax[j].y), fminf(ax[j].z, ax[j].w)));
        xmx = fmaxf(xmx, fmaxf(fmaxf(ax[j].x, ax[j].y), fmaxf(ax[j].z, ax[j].w)));
        ymn = fminf(ymn, fminf(fminf(ay[j].x, ay[j].y), fminf(ay[j].z, ay[j].w)));
        ymx = fmaxf(ymx, fmaxf(fmaxf(ay[j].x, ay[j].y), fmaxf(ay[j].z, ay[j].w)));
    }

    #pragma unroll
    for (int off = 16; off > 0; off >>= 1) {
        xmn = fminf(xmn, __shfl_xor_sync(0xFFFFFFFFu, xmn, off));
        xmx = fmaxf(xmx, __shfl_xor_sync(0xFFFFFFFFu, xmx, off));
        ymn = fminf(ymn, __shfl_xor_sync(0xFFFFFFFFu, ymn, off));
        ymx = fmaxf(ymx, __shfl_xor_sync(0xFFFFFFFFu, ymx, off));
    }

    __shared__ float4 s[8];
    const int wid = threadIdx.x >> 5;
    const int lid = threadIdx.x & 31;
    if (lid == 0) s[wid] = make_float4(xmn, xmx, ymn, ymx);
    __syncthreads();
    if (threadIdx.x == 0) {
        float4 r = s[0];
        #pragma unroll
        for (int w = 1; w < 8; w++) {
            r.x = fminf(r.x, s[w].x);
            r.y = fmaxf(r.y, s[w].y);
            r.z = fminf(r.z, s[w].z);
            r.w = fmaxf(r.w, s[w].w);
        }
        g_part[b][blockIdx.x] = r;
    }
}

// Scatter: launched with PDL. Payload loads (independent of minmax) are issued
// first; cudaGridDependencySynchronize() gates the bounds read + atomics.
constexpr int TPB = 256;
constexpr int IT  = 16;

__global__ __launch_bounds__(TPB) void scatter_kernel(
    const float*  __restrict__ point_rates,
    const float2* __restrict__ coords,
    float*        __restrict__ out)
{
    const int b = blockIdx.y;
    const float* pr = point_rates + (size_t)b * NS;
    float* ob = out + (size_t)b * HWSZ;

    const int base = blockIdx.x * (TPB * IT) + threadIdx.x;

    // Payload loads: inputs only — safe to issue while minmax still runs.
    float2 c[IT];
    float  rate[IT];
    #pragma unroll
    for (int j = 0; j < IT; j++) c[j] = coords[base + j * TPB];
    #pragma unroll
    for (int j = 0; j < IT; j++) rate[j] = pr[base + j * TPB];

    // Wait for minmax grid completion (bounds written, out zeroed).
    cudaGridDependencySynchronize();

    // Bounds prologue: one warp reduces the SEGS(=32) partials, one per lane.
    __shared__ float4 sb;
    if (threadIdx.x < 32) {
        float4 p = g_part[b][threadIdx.x];
        float xmn = p.x, xmx = p.y, ymn = p.z, ymx = p.w;
        #pragma unroll
        for (int off = 16; off > 0; off >>= 1) {
            xmn = fminf(xmn, __shfl_xor_sync(0xFFFFFFFFu, xmn, off));
            xmx = fmaxf(xmx, __shfl_xor_sync(0xFFFFFFFFu, xmx, off));
            ymn = fminf(ymn, __shfl_xor_sync(0xFFFFFFFFu, ymn, off));
            ymx = fmaxf(ymx, __shfl_xor_sync(0xFFFFFFFFu, ymx, off));
        }
        if (threadIdx.x == 0) sb = make_float4(xmn, xmx, ymn, ymx);
    }
    __syncthreads();

    const float xmin = sb.x, xmax = sb.y, ymin = sb.z, ymax = sb.w;
    const float dx = __fsub_rn(xmax, xmin);
    const float dy = __fsub_rn(ymax, ymin);

    #pragma unroll
    for (int j = 0; j < IT; j++) {
        const bool iv = (c[j].x >= xmin) && (c[j].x <= xmax) &&
                        (c[j].y >= ymin) && (c[j].y <= ymax);
        // Match reference bit-exactly: strict IEEE rn sub/div/mul, then
        // round-half-even (== jnp.round) before clip.
        const float nx = __fdiv_rn(__fsub_rn(c[j].x, xmin), dx);
        const float ny = __fdiv_rn(__fsub_rn(c[j].y, ymin), dy);
        int px = __float2int_rn(__fmul_rn(nx, 255.0f));
        int py = __float2int_rn(__fmul_rn(ny, 255.0f));
        px = min(max(px, 0), WW - 1);
        py = min(max(py, 0), HH - 1);
        if (iv) {
            atomicAdd(&ob[py * WW + px], rate[j]);   // RED.ADD, no return
        }
    }
}

// Streaming finalize (PDL): prefetch gia before the grid-dep sync, then
// read the accumulated field and multiply.
constexpr int MTPB = 256;
constexpr int MIT  = 2;

__global__ __launch_bounds__(MTPB) void mul_kernel(const float4* __restrict__ gia,
                                                   float4* __restrict__ out,
                                                   int n4)
{
    const int i0 = blockIdx.x * MTPB + threadIdx.x;
    const int stride = gridDim.x * MTPB;

    float4 g[MIT];
    #pragma unroll
    for (int j = 0; j < MIT; j++) {
        const int i = i0 + j * stride;
        if (i < n4) g[j] = gia[i];
    }

    cudaGridDependencySynchronize();

    #pragma unroll
    for (int j = 0; j < MIT; j++) {
        const int i = i0 + j * stride;
        if (i < n4) {
            float4 o = out[i];
            o.x = __fmul_rn(o.x, g[j].x);
            o.y = __fmul_rn(o.y, g[j].y);
            o.z = __fmul_rn(o.z, g[j].z);
            o.w = __fmul_rn(o.w, g[j].w);
            out[i] = o;
        }
    }
}

extern "C" void kernel_launch(void* const* d_in, const int* in_sizes, int n_in,
                              void* d_out, int out_size)
{
    const float*  point_rates = (const float*)d_in[0];   // (B, NS)
    const float*  spatial     = (const float*)d_in[1];   // (B, 2, H, W)
    const float*  gia         = (const float*)d_in[2];   // (B, H, W)
    const float2* coords      = (const float2*)d_in[3];  // (NS, 2)
    float* out = (float*)d_out;                          // (B, 1, H, W)

    // 1) minmax partials + output zeroing (plain launch)
    dim3 mg(SEGS, BB);
    minmax_kernel<<<mg, 256>>>(spatial, (float4*)out);

    cudaLaunchAttribute pdl[1];
    pdl[0].id = cudaLaunchAttributeProgrammaticStreamSerialization;
    pdl[0].val.programmaticStreamSerializationAllowed = 1;

    // 2) scatter with PDL: overlaps its payload loads with minmax
    {
        cudaLaunchConfig_t cfg = {};
        cfg.gridDim = dim3(NS / (TPB * IT), BB);
        cfg.blockDim = dim3(TPB);
        cfg.stream = 0;
        cfg.attrs = pdl;
        cfg.numAttrs = 1;
        cudaLaunchKernelEx(&cfg, scatter_kernel, point_rates, coords, out);
    }

    // 3) mul with PDL: overlaps gia prefetch with scatter tail
    {
        const int n4 = (BB * HWSZ) / 4;   // 524288
        cudaLaunchConfig_t cfg = {};
        cfg.gridDim = dim3(n4 / (MTPB * MIT));
        cfg.blockDim = dim3(MTPB);
        cfg.stream = 0;
        cfg.attrs = pdl;
        cfg.numAttrs = 1;
        cudaLaunchKernelEx(&cfg, mul_kernel, (const float4*)gia, (float4*)out, n4);
    }
}